// round 1
// baseline (speedup 1.0000x reference)
#include <cuda_runtime.h>
#include <math.h>

#define Bn   16
#define En   1024
#define Hn   16
#define Nn   2048
#define EHn  64
#define BHn  256
#define NM1n 2047

// ---------------- scratch (static __device__, no allocations) ----------------
__device__ float g_qstep[BHn * EHn];
__device__ float g_kstep[BHn * EHn];
__device__ float g_vstep[BHn * EHn];
__device__ float g_alr0[BHn * NM1n];
__device__ float g_alr1[BHn * NM1n];
__device__ float g_atb [BHn * NM1n];
__device__ float g_abr [BHn];
__device__ float g_atbsum[BHn];
__device__ float g_avbot[BHn * EHn];
__device__ float g_attn[(size_t)Nn * Bn * En];   // attn in (n, b, h*64+e) layout = GEMM A

// ---------------- kernel 1: qkv projections ----------------
// one warp per output element; q pre-scaled by 1/sqrt(Eh)
__global__ __launch_bounds__(256) void proj_kernel(
    const float* __restrict__ query, const float* __restrict__ key,
    const float* __restrict__ value, const float* __restrict__ W,
    const float* __restrict__ bias)
{
    int w = blockIdx.x * 8 + (threadIdx.x >> 5);
    int lane = threadIdx.x & 31;
    int c = w & 1023;
    int r = (w >> 10) & 15;
    int p = w >> 14;                       // 0=q, 1=k, 2=v
    const float* in = (p == 0) ? query : (p == 1) ? key : value;
    const float* wr = W + (size_t)(p * En + c) * En;
    const float* ir = in + r * En;
    float acc = 0.f;
    for (int k = lane; k < En; k += 32) acc += ir[k] * wr[k];
    #pragma unroll
    for (int o = 16; o; o >>= 1) acc += __shfl_down_sync(0xffffffffu, acc, o);
    if (lane == 0) {
        acc += bias[p * En + c];
        int h = c >> 6, e = c & 63;
        int bh = r * Hn + h;
        if (p == 0)      g_qstep[bh * EHn + e] = acc * 0.125f;
        else if (p == 1) g_kstep[bh * EHn + e] = acc;
        else             g_vstep[bh * EHn + e] = acc;
    }
}

// ---------------- kernel 2: a_tb1 = exp(q_step @ k_t[:,:,1:]) + fused k_t shift-copy
// also a_br and a_tb row-sum
__global__ __launch_bounds__(256) void atb_kernel(
    const float* __restrict__ k_t_mem, float* __restrict__ k_t_out)
{
    int bh = blockIdx.x;
    int tid = threadIdx.x;
    __shared__ float qs[EHn], ks[EHn];
    __shared__ float red[256];
    if (tid < EHn) {
        qs[tid] = g_qstep[bh * EHn + tid];
        ks[tid] = g_kstep[bh * EHn + tid];
    }
    __syncthreads();
    const float* base  = k_t_mem + (size_t)bh * EHn * Nn;
    float*       obase = k_t_out + (size_t)bh * EHn * Nn;
    float acc[8];
    #pragma unroll
    for (int j = 0; j < 8; j++) acc[j] = 0.f;
    for (int e = 0; e < EHn; e++) {
        const float* row = base + (size_t)e * Nn;
        float* orow = obase + (size_t)e * Nn;
        float q = qs[e];
        #pragma unroll
        for (int j = 0; j < 8; j++) {
            int s = tid + 256 * j;
            float v = row[s];
            acc[j] += q * v;
            if (s >= 1) orow[s - 1] = v;       // fused shifted copy
        }
    }
    if (tid < EHn) obase[(size_t)tid * Nn + (Nn - 1)] = ks[tid];  // append k_step
    float local = 0.f;
    #pragma unroll
    for (int j = 0; j < 8; j++) {
        int s = tid + 256 * j;
        if (s >= 1) {
            float a = expf(acc[j]);
            g_atb[bh * NM1n + (s - 1)] = a;
            local += a;
        }
    }
    red[tid] = local;
    __syncthreads();
    for (int st = 128; st > 0; st >>= 1) {
        if (tid < st) red[tid] += red[tid + st];
        __syncthreads();
    }
    if (tid == 0) g_atbsum[bh] = red[0];
    __syncthreads();
    red[tid] = (tid < EHn) ? qs[tid] * ks[tid] : 0.f;
    __syncthreads();
    for (int st = 128; st > 0; st >>= 1) {
        if (tid < st) red[tid] += red[tid + st];
        __syncthreads();
    }
    if (tid == 0) g_abr[bh] = expf(red[0]);
}

// ---------------- kernel 3: a_lr = exp(q_mem[:,1:] @ {k_old, k_step}) + fused q shift-copy
__global__ __launch_bounds__(256) void alr_kernel(
    const float* __restrict__ q_mem, const float* __restrict__ k_t_mem,
    float* __restrict__ q_out)
{
    int bh = blockIdx.x;
    int tid = threadIdx.x, lane = tid & 31, warp = tid >> 5;
    __shared__ float kold[EHn], ks[EHn];
    if (tid < EHn) {
        kold[tid] = k_t_mem[(size_t)bh * EHn * Nn + (size_t)tid * Nn]; // column 0
        ks[tid]   = g_kstep[bh * EHn + tid];
    }
    __syncthreads();
    const float* qbase  = q_mem + (size_t)bh * Nn * EHn;
    float*       qobase = q_out + (size_t)bh * Nn * EHn;
    for (int n = 1 + warp; n < Nn; n += 8) {
        const float* row = qbase + (size_t)n * EHn;
        float q0 = row[lane], q1 = row[lane + 32];
        float* orow = qobase + (size_t)(n - 1) * EHn;
        orow[lane] = q0; orow[lane + 32] = q1;           // fused shifted copy
        float d0 = q0 * kold[lane] + q1 * kold[lane + 32];
        float d1 = q0 * ks[lane]   + q1 * ks[lane + 32];
        #pragma unroll
        for (int o = 16; o; o >>= 1) {
            d0 += __shfl_down_sync(0xffffffffu, d0, o);
            d1 += __shfl_down_sync(0xffffffffu, d1, o);
        }
        if (lane == 0) {
            g_alr0[bh * NM1n + n - 1] = expf(d0);
            g_alr1[bh * NM1n + n - 1] = expf(d1);
        }
    }
    if (tid < EHn) qobase[(size_t)(Nn - 1) * EHn + tid] = g_qstep[bh * EHn + tid];
}

// ---------------- kernel 4: av_bot = a_tb1 @ v_mem[:,1:] + a_br*v_step  + fused v shift-copy
__global__ __launch_bounds__(256) void avbot_kernel(
    const float* __restrict__ v_mem, float* __restrict__ v_out)
{
    int bh = blockIdx.x, tid = threadIdx.x;
    int e = tid & 63, ch = tid >> 6;   // 4 chunks
    const float* vbase  = v_mem + (size_t)bh * Nn * EHn;
    float*       vobase = v_out + (size_t)bh * Nn * EHn;
    const float* atb = g_atb + bh * NM1n;
    float acc = 0.f;
    for (int s = ch; s < NM1n; s += 4) {
        float v = vbase[(size_t)(s + 1) * EHn + e];
        vobase[(size_t)s * EHn + e] = v;                 // fused shifted copy
        acc += atb[s] * v;
    }
    __shared__ float part[4][EHn];
    part[ch][e] = acc;
    __syncthreads();
    if (tid < EHn) {
        float vs = g_vstep[bh * EHn + tid];
        float t = part[0][tid] + part[1][tid] + part[2][tid] + part[3][tid]
                + g_abr[bh] * vs;
        g_avbot[bh * EHn + tid] = t;
        vobase[(size_t)(Nn - 1) * EHn + tid] = vs;       // append v_step
    }
}

// ---------------- kernel 5: av_top / a_sum / attn-layout transpose + new-state writes ----
__global__ __launch_bounds__(256) void ew_kernel(
    const float* __restrict__ a_sum_mem, const float* __restrict__ av_mem,
    const float* __restrict__ v_mem,
    float* __restrict__ a_sum_out, float* __restrict__ av_out)
{
    int tid = threadIdx.x;
    int e = tid & 63;
    int rid = blockIdx.x * 4 + (tid >> 6);
    int bh = rid >> 11, n = rid & (Nn - 1);
    int b = bh >> 4, h = bh & 15;
    float* attn_row = g_attn + ((size_t)(n * Bn + b) * En + h * EHn);
    if (n < NM1n) {
        float al0 = g_alr0[bh * NM1n + n];
        float al1 = g_alr1[bh * NM1n + n];
        float asum = a_sum_mem[bh * NM1n + n] + al1 - al0;
        float v0 = v_mem[(size_t)bh * Nn * EHn + e];       // v_mem row 0
        float vs = g_vstep[bh * EHn + e];
        float av = av_mem[((size_t)bh * NM1n + n) * EHn + e] - al0 * v0 + al1 * vs;
        attn_row[e] = av / asum;
        if (n >= 1) {
            av_out[((size_t)bh * NM1n + (n - 1)) * EHn + e] = av;
            if (e == 0) a_sum_out[bh * NM1n + n - 1] = asum;
        }
    } else {
        float asum = g_atbsum[bh] + g_abr[bh];
        float av = g_avbot[bh * EHn + e];
        attn_row[e] = av / asum;
        av_out[((size_t)bh * NM1n + NM1n - 1) * EHn + e] = av;
        if (e == 0) a_sum_out[bh * NM1n + NM1n - 1] = asum;
    }
}

// ---------------- kernel 6: out = attn @ W_out^T + bias  (tf32 mma.sync) ----------------
__device__ __forceinline__ unsigned f2tf(float f) {
    unsigned u; asm("cvt.rna.tf32.f32 %0, %1;" : "=r"(u) : "f"(f)); return u;
}
__device__ __forceinline__ void mma_tf32(float c[4], const unsigned a[4], const unsigned b[2]) {
    asm volatile(
        "mma.sync.aligned.m16n8k8.row.col.f32.tf32.tf32.f32 "
        "{%0,%1,%2,%3},{%4,%5,%6,%7},{%8,%9},{%0,%1,%2,%3};\n"
        : "+f"(c[0]), "+f"(c[1]), "+f"(c[2]), "+f"(c[3])
        : "r"(a[0]), "r"(a[1]), "r"(a[2]), "r"(a[3]), "r"(b[0]), "r"(b[1]));
}

__global__ __launch_bounds__(256) void gemm_kernel(
    const float* __restrict__ W, const float* __restrict__ bias,
    float* __restrict__ out)
{
    const int K = En;                        // 1024
    __shared__ float As[128][36];            // pad 4 -> conflict-free frag loads
    __shared__ float Bs[128][36];
    int tid = threadIdx.x;
    int warp = tid >> 5, lane = tid & 31;
    int warp_m = warp >> 2, warp_n = warp & 3;   // 2x4 warp grid, warp tile 64x32
    int m0 = blockIdx.y * 128;
    int n0 = blockIdx.x * 128;
    const float* Ag = g_attn + (size_t)m0 * K;
    const float* Bg = W + (size_t)n0 * K;

    float c[4][4][4];
    #pragma unroll
    for (int i = 0; i < 4; i++)
        #pragma unroll
        for (int j = 0; j < 4; j++)
            #pragma unroll
            for (int k = 0; k < 4; k++) c[i][j][k] = 0.f;

    for (int kb = 0; kb < K; kb += 32) {
        __syncthreads();
        #pragma unroll
        for (int i = 0; i < 4; i++) {
            int t = tid + 256 * i;
            int row = t >> 3;
            int colv = (t & 7) << 2;
            float4 va = *(const float4*)(Ag + (size_t)row * K + kb + colv);
            *(float4*)(&As[row][colv]) = va;
            float4 vb = *(const float4*)(Bg + (size_t)row * K + kb + colv);
            *(float4*)(&Bs[row][colv]) = vb;
        }
        __syncthreads();
        #pragma unroll
        for (int kk = 0; kk < 32; kk += 8) {
            unsigned a[4][4], bfr[4][2];
            int ar = warp_m * 64 + (lane >> 2);
            int kc = kk + (lane & 3);
            #pragma unroll
            for (int mf = 0; mf < 4; mf++) {
                int r = ar + mf * 16;
                a[mf][0] = f2tf(As[r][kc]);
                a[mf][1] = f2tf(As[r + 8][kc]);
                a[mf][2] = f2tf(As[r][kc + 4]);
                a[mf][3] = f2tf(As[r + 8][kc + 4]);
            }
            int bc = warp_n * 32 + (lane >> 2);
            #pragma unroll
            for (int nf = 0; nf < 4; nf++) {
                bfr[nf][0] = f2tf(Bs[bc + nf * 8][kc]);
                bfr[nf][1] = f2tf(Bs[bc + nf * 8][kc + 4]);
            }
            #pragma unroll
            for (int mf = 0; mf < 4; mf++)
                #pragma unroll
                for (int nf = 0; nf < 4; nf++)
                    mma_tf32(c[mf][nf], a[mf], bfr[nf]);
        }
    }
    #pragma unroll
    for (int mf = 0; mf < 4; mf++) {
        int r = m0 + warp_m * 64 + mf * 16 + (lane >> 2);
        #pragma unroll
        for (int nf = 0; nf < 4; nf++) {
            int cc = n0 + warp_n * 32 + nf * 8 + ((lane & 3) << 1);
            float b0 = bias[cc], b1 = bias[cc + 1];
            out[(size_t)r * En + cc]           = c[mf][nf][0] + b0;
            out[(size_t)r * En + cc + 1]       = c[mf][nf][1] + b1;
            out[(size_t)(r + 8) * En + cc]     = c[mf][nf][2] + b0;
            out[(size_t)(r + 8) * En + cc + 1] = c[mf][nf][3] + b1;
        }
    }
}

// ---------------- launch ----------------
extern "C" void kernel_launch(void* const* d_in, const int* in_sizes, int n_in,
                              void* d_out, int out_size)
{
    const float* query     = (const float*)d_in[0];
    const float* key       = (const float*)d_in[1];
    const float* value     = (const float*)d_in[2];
    const float* a_sum_mem = (const float*)d_in[3];
    const float* av_mem    = (const float*)d_in[4];
    const float* q_mem     = (const float*)d_in[5];
    const float* k_t_mem   = (const float*)d_in[6];
    const float* v_mem     = (const float*)d_in[7];
    const float* ipw       = (const float*)d_in[8];
    const float* ipb       = (const float*)d_in[9];
    const float* opw       = (const float*)d_in[10];
    const float* opb       = (const float*)d_in[11];

    float* out       = (float*)d_out;
    float* a_sum_out = out + (size_t)Nn * Bn * En;
    float* av_out    = a_sum_out + (size_t)BHn * NM1n;
    float* q_out     = av_out + (size_t)BHn * NM1n * EHn;
    float* kt_out    = q_out + (size_t)BHn * Nn * EHn;
    float* v_out     = kt_out + (size_t)BHn * Nn * EHn;

    proj_kernel<<<6144, 256>>>(query, key, value, ipw, ipb);
    atb_kernel<<<BHn, 256>>>(k_t_mem, kt_out);
    alr_kernel<<<BHn, 256>>>(q_mem, k_t_mem, q_out);
    avbot_kernel<<<BHn, 256>>>(v_mem, v_out);
    ew_kernel<<<BHn * Nn / 4, 256>>>(a_sum_mem, av_mem, v_mem, a_sum_out, av_out);
    dim3 g(En / 128, (Nn * Bn) / 128);
    gemm_kernel<<<g, 256>>>(opw, opb, out);
}

// round 2
// speedup vs baseline: 1.3457x; 1.3457x over previous
#include <cuda_runtime.h>
#include <math.h>

#define Bn   16
#define En   1024
#define Hn   16
#define Nn   2048
#define EHn  64
#define BHn  256
#define NM1n 2047

// ---------------- scratch ----------------
__device__ float g_qstep[BHn * EHn];
__device__ float g_kstep[BHn * EHn];
__device__ float g_vstep[BHn * EHn];
__device__ float g_alr0[BHn * NM1n];
__device__ float g_alr1[BHn * NM1n];
__device__ float g_atb [BHn * NM1n];
__device__ float g_abr [BHn];
__device__ float g_atbsum_part[BHn * 4];
__device__ float g_avbot_part[BHn * 8 * EHn];
__device__ float g_attn[(size_t)Nn * Bn * En];   // A for GEMM, tf32-pre-rounded
__device__ float g_wtf[(size_t)En * En];         // W_out tf32-pre-rounded

__device__ __forceinline__ float tf32r(float f) {
    unsigned u; asm("cvt.rna.tf32.f32 %0, %1;" : "=r"(u) : "f"(f));
    return __uint_as_float(u);
}

// ---------------- kernel 0: pre-round W_out to tf32 ----------------
__global__ __launch_bounds__(256) void wround_kernel(const float* __restrict__ W) {
    int i = (blockIdx.x * 256 + threadIdx.x) * 4;
    float4 v = *(const float4*)(W + i);
    v.x = tf32r(v.x); v.y = tf32r(v.y); v.z = tf32r(v.z); v.w = tf32r(v.w);
    *(float4*)(g_wtf + i) = v;
}

// ---------------- kernel 1: qkv projections ----------------
__global__ __launch_bounds__(256) void proj_kernel(
    const float* __restrict__ query, const float* __restrict__ key,
    const float* __restrict__ value, const float* __restrict__ W,
    const float* __restrict__ bias)
{
    int w = blockIdx.x * 8 + (threadIdx.x >> 5);
    int lane = threadIdx.x & 31;
    int c = w & 1023;
    int r = (w >> 10) & 15;
    int p = w >> 14;
    const float* in = (p == 0) ? query : (p == 1) ? key : value;
    const float* wr = W + (size_t)(p * En + c) * En;
    const float* ir = in + r * En;
    float acc = 0.f;
    for (int k = lane; k < En; k += 32) acc += ir[k] * wr[k];
    #pragma unroll
    for (int o = 16; o; o >>= 1) acc += __shfl_down_sync(0xffffffffu, acc, o);
    if (lane == 0) {
        acc += bias[p * En + c];
        int h = c >> 6, e = c & 63;
        int bh = r * Hn + h;
        if (p == 0)      g_qstep[bh * EHn + e] = acc * 0.125f;
        else if (p == 1) g_kstep[bh * EHn + e] = acc;
        else             g_vstep[bh * EHn + e] = acc;
    }
}

// ---------------- kernel 2: a_tb1 + fused k_t shift-copy (4 chunks/bh) ----------------
__global__ __launch_bounds__(256) void atb_kernel(
    const float* __restrict__ k_t_mem, float* __restrict__ k_t_out)
{
    int bh = blockIdx.x, ck = blockIdx.y;        // ck in [0,4)
    int tid = threadIdx.x;
    int s0 = ck * 512;
    __shared__ float qs[EHn], ks[EHn];
    __shared__ float red[256];
    if (tid < EHn) {
        qs[tid] = g_qstep[bh * EHn + tid];
        ks[tid] = g_kstep[bh * EHn + tid];
    }
    __syncthreads();
    const float* base  = k_t_mem + (size_t)bh * EHn * Nn;
    float*       obase = k_t_out + (size_t)bh * EHn * Nn;
    float acc0 = 0.f, acc1 = 0.f;
    int sA = s0 + tid, sB = s0 + tid + 256;
    for (int e = 0; e < EHn; e++) {
        const float* row = base + (size_t)e * Nn;
        float* orow = obase + (size_t)e * Nn;
        float q = qs[e];
        float vA = row[sA], vB = row[sB];
        acc0 += q * vA; acc1 += q * vB;
        if (sA >= 1) orow[sA - 1] = vA;
        orow[sB - 1] = vB;
    }
    if (ck == 3 && tid < EHn) obase[(size_t)tid * Nn + (Nn - 1)] = ks[tid];
    float local = 0.f;
    if (sA >= 1) { float a = expf(acc0); g_atb[bh * NM1n + sA - 1] = a; local += a; }
    { float a = expf(acc1); g_atb[bh * NM1n + sB - 1] = a; local += a; }
    red[tid] = local;
    __syncthreads();
    for (int st = 128; st > 0; st >>= 1) {
        if (tid < st) red[tid] += red[tid + st];
        __syncthreads();
    }
    if (tid == 0) g_atbsum_part[bh * 4 + ck] = red[0];
    if (ck == 0) {
        __syncthreads();
        red[tid] = (tid < EHn) ? qs[tid] * ks[tid] : 0.f;
        __syncthreads();
        for (int st = 128; st > 0; st >>= 1) {
            if (tid < st) red[tid] += red[tid + st];
            __syncthreads();
        }
        if (tid == 0) g_abr[bh] = expf(red[0]);
    }
}

// ---------------- kernel 3: a_lr + fused q shift-copy (4 chunks/bh) ----------------
__global__ __launch_bounds__(256) void alr_kernel(
    const float* __restrict__ q_mem, const float* __restrict__ k_t_mem,
    float* __restrict__ q_out)
{
    int bh = blockIdx.x, ck = blockIdx.y;
    int tid = threadIdx.x, lane = tid & 31, warp = tid >> 5;
    __shared__ float kold[EHn], ks[EHn];
    if (tid < EHn) {
        kold[tid] = k_t_mem[(size_t)bh * EHn * Nn + (size_t)tid * Nn];
        ks[tid]   = g_kstep[bh * EHn + tid];
    }
    __syncthreads();
    const float* qbase  = q_mem + (size_t)bh * Nn * EHn;
    float*       qobase = q_out + (size_t)bh * Nn * EHn;
    int nlo = (ck == 0) ? 1 : ck * 512;
    int nhi = ck * 512 + 512;
    for (int n = nlo + warp; n < nhi; n += 8) {
        const float* row = qbase + (size_t)n * EHn;
        float q0 = row[lane], q1 = row[lane + 32];
        float* orow = qobase + (size_t)(n - 1) * EHn;
        orow[lane] = q0; orow[lane + 32] = q1;
        float d0 = q0 * kold[lane] + q1 * kold[lane + 32];
        float d1 = q0 * ks[lane]   + q1 * ks[lane + 32];
        #pragma unroll
        for (int o = 16; o; o >>= 1) {
            d0 += __shfl_down_sync(0xffffffffu, d0, o);
            d1 += __shfl_down_sync(0xffffffffu, d1, o);
        }
        if (lane == 0) {
            g_alr0[bh * NM1n + n - 1] = expf(d0);
            g_alr1[bh * NM1n + n - 1] = expf(d1);
        }
    }
    if (ck == 3 && tid < EHn)
        qobase[(size_t)(Nn - 1) * EHn + tid] = g_qstep[bh * EHn + tid];
}

// ---------------- kernel 4: av_bot partials + fused v shift-copy (8 chunks/bh) -------
__global__ __launch_bounds__(256) void avbot_kernel(
    const float* __restrict__ v_mem, float* __restrict__ v_out)
{
    int bh = blockIdx.x, ck = blockIdx.y;        // ck in [0,8)
    int tid = threadIdx.x;
    int e = tid & 63, ch = tid >> 6;
    int s0 = ck * 256;
    int s1 = (ck == 7) ? NM1n : s0 + 256;
    const float* vbase  = v_mem + (size_t)bh * Nn * EHn;
    float*       vobase = v_out + (size_t)bh * Nn * EHn;
    const float* atb = g_atb + bh * NM1n;
    float acc = 0.f;
    for (int s = s0 + ch; s < s1; s += 4) {
        float v = vbase[(size_t)(s + 1) * EHn + e];
        vobase[(size_t)s * EHn + e] = v;
        acc += atb[s] * v;
    }
    __shared__ float part[4][EHn];
    part[ch][e] = acc;
    __syncthreads();
    if (tid < EHn) {
        g_avbot_part[((size_t)bh * 8 + ck) * EHn + tid] =
            part[0][tid] + part[1][tid] + part[2][tid] + part[3][tid];
        if (ck == 7)
            vobase[(size_t)(Nn - 1) * EHn + tid] = g_vstep[bh * EHn + tid];
    }
}

// ---------------- kernel 5: av_top / a_sum / attn (tf32-rounded) ----------------
__global__ __launch_bounds__(256) void ew_kernel(
    const float* __restrict__ a_sum_mem, const float* __restrict__ av_mem,
    const float* __restrict__ v_mem,
    float* __restrict__ a_sum_out, float* __restrict__ av_out)
{
    int tid = threadIdx.x;
    int e = tid & 63;
    int rid = blockIdx.x * 4 + (tid >> 6);
    int bh = rid >> 11, n = rid & (Nn - 1);
    int b = bh >> 4, h = bh & 15;
    float* attn_row = g_attn + ((size_t)(n * Bn + b) * En + h * EHn);
    if (n < NM1n) {
        float al0 = g_alr0[bh * NM1n + n];
        float al1 = g_alr1[bh * NM1n + n];
        float asum = a_sum_mem[bh * NM1n + n] + al1 - al0;
        float v0 = v_mem[(size_t)bh * Nn * EHn + e];
        float vs = g_vstep[bh * EHn + e];
        float av = av_mem[((size_t)bh * NM1n + n) * EHn + e] - al0 * v0 + al1 * vs;
        attn_row[e] = tf32r(av / asum);
        if (n >= 1) {
            av_out[((size_t)bh * NM1n + (n - 1)) * EHn + e] = av;
            if (e == 0) a_sum_out[bh * NM1n + n - 1] = asum;
        }
    } else {
        float abr = g_abr[bh];
        float asum = g_atbsum_part[bh * 4] + g_atbsum_part[bh * 4 + 1]
                   + g_atbsum_part[bh * 4 + 2] + g_atbsum_part[bh * 4 + 3] + abr;
        float av = abr * g_vstep[bh * EHn + e];
        #pragma unroll
        for (int c = 0; c < 8; c++)
            av += g_avbot_part[((size_t)bh * 8 + c) * EHn + e];
        attn_row[e] = tf32r(av / asum);
        av_out[((size_t)bh * NM1n + NM1n - 1) * EHn + e] = av;
        if (e == 0) a_sum_out[bh * NM1n + NM1n - 1] = asum;
    }
}

// ---------------- kernel 6: out = attn @ W^T + bias (tf32, cp.async + ldmatrix) ------
__device__ __forceinline__ void mma_tf32(float c[4], const unsigned a[4], const unsigned b[2]) {
    asm volatile(
        "mma.sync.aligned.m16n8k8.row.col.f32.tf32.tf32.f32 "
        "{%0,%1,%2,%3},{%4,%5,%6,%7},{%8,%9},{%0,%1,%2,%3};\n"
        : "+f"(c[0]), "+f"(c[1]), "+f"(c[2]), "+f"(c[3])
        : "r"(a[0]), "r"(a[1]), "r"(a[2]), "r"(a[3]), "r"(b[0]), "r"(b[1]));
}
__device__ __forceinline__ void ldsm4(unsigned& r0, unsigned& r1, unsigned& r2, unsigned& r3,
                                      unsigned addr) {
    asm volatile("ldmatrix.sync.aligned.m8n8.x4.shared.b16 {%0,%1,%2,%3}, [%4];"
                 : "=r"(r0), "=r"(r1), "=r"(r2), "=r"(r3) : "r"(addr));
}
__device__ __forceinline__ void cpa16(unsigned dst, const float* src) {
    asm volatile("cp.async.cg.shared.global [%0], [%1], 16;" :: "r"(dst), "l"(src));
}

#define KB 16
#define LDP 20   // padded row stride (floats)

__global__ __launch_bounds__(256) void gemm_kernel(
    const float* __restrict__ bias, float* __restrict__ out)
{
    const int K = En;
    __shared__ float As[2][128][LDP];
    __shared__ float Bs[2][128][LDP];
    int tid = threadIdx.x;
    int warp = tid >> 5, lane = tid & 31;
    int warp_m = warp >> 2, warp_n = warp & 3;
    int m0 = blockIdx.y * 128;
    int n0 = blockIdx.x * 128;
    const float* Ag = g_attn + (size_t)m0 * K;
    const float* Bg = g_wtf + (size_t)n0 * K;

    unsigned sA = (unsigned)__cvta_generic_to_shared(&As[0][0][0]);
    unsigned sB = (unsigned)__cvta_generic_to_shared(&Bs[0][0][0]);
    const unsigned BUFB = 128 * LDP * 4;

    // per-thread tile-load coords: 2 rows x 1 float4 chunk per array
    int lrow = tid >> 2;            // 0..63
    int lcol = (tid & 3) << 2;      // 0,4,8,12

    float c[4][4][4];
    #pragma unroll
    for (int i = 0; i < 4; i++)
        #pragma unroll
        for (int j = 0; j < 4; j++)
            #pragma unroll
            for (int k = 0; k < 4; k++) c[i][j][k] = 0.f;

    // prologue: tile 0 -> buf 0
    {
        cpa16(sA + (lrow * LDP + lcol) * 4,        Ag + (size_t)lrow * K + lcol);
        cpa16(sA + ((lrow + 64) * LDP + lcol) * 4, Ag + (size_t)(lrow + 64) * K + lcol);
        cpa16(sB + (lrow * LDP + lcol) * 4,        Bg + (size_t)lrow * K + lcol);
        cpa16(sB + ((lrow + 64) * LDP + lcol) * 4, Bg + (size_t)(lrow + 64) * K + lcol);
        asm volatile("cp.async.commit_group;");
    }

    const int T = K / KB;   // 64
    int ltile = lane >> 3, lrowin = lane & 7;

    for (int t = 0; t < T; t++) {
        if (t + 1 < T) {
            int kb = (t + 1) * KB;
            unsigned boff = ((t + 1) & 1) ? BUFB : 0;
            cpa16(sA + boff + (lrow * LDP + lcol) * 4,        Ag + (size_t)lrow * K + kb + lcol);
            cpa16(sA + boff + ((lrow + 64) * LDP + lcol) * 4, Ag + (size_t)(lrow + 64) * K + kb + lcol);
            cpa16(sB + boff + (lrow * LDP + lcol) * 4,        Bg + (size_t)lrow * K + kb + lcol);
            cpa16(sB + boff + ((lrow + 64) * LDP + lcol) * 4, Bg + (size_t)(lrow + 64) * K + kb + lcol);
            asm volatile("cp.async.commit_group;");
            asm volatile("cp.async.wait_group 1;");
        } else {
            asm volatile("cp.async.wait_group 0;");
        }
        __syncthreads();
        unsigned aoff = (t & 1) ? BUFB : 0;
        #pragma unroll
        for (int kk = 0; kk < KB; kk += 8) {
            unsigned a[4][4], bf[4][2];
            #pragma unroll
            for (int mf = 0; mf < 4; mf++) {
                int r = warp_m * 64 + mf * 16 + ((ltile & 1) << 3) + lrowin;
                int col = kk + ((ltile >> 1) << 2);
                ldsm4(a[mf][0], a[mf][1], a[mf][2], a[mf][3],
                      sA + aoff + (unsigned)(r * LDP + col) * 4);
            }
            #pragma unroll
            for (int np = 0; np < 2; np++) {
                int r = warp_n * 32 + np * 16 + ((ltile >> 1) << 3) + lrowin;
                int col = kk + ((ltile & 1) << 2);
                ldsm4(bf[2 * np][0], bf[2 * np][1], bf[2 * np + 1][0], bf[2 * np + 1][1],
                      sB + aoff + (unsigned)(r * LDP + col) * 4);
            }
            #pragma unroll
            for (int mf = 0; mf < 4; mf++)
                #pragma unroll
                for (int nf = 0; nf < 4; nf++)
                    mma_tf32(c[mf][nf], a[mf], bf[nf]);
        }
        __syncthreads();
    }

    #pragma unroll
    for (int mf = 0; mf < 4; mf++) {
        int r = m0 + warp_m * 64 + mf * 16 + (lane >> 2);
        #pragma unroll
        for (int nf = 0; nf < 4; nf++) {
            int cc = n0 + warp_n * 32 + nf * 8 + ((lane & 3) << 1);
            float b0 = bias[cc], b1 = bias[cc + 1];
            out[(size_t)r * En + cc]           = c[mf][nf][0] + b0;
            out[(size_t)r * En + cc + 1]       = c[mf][nf][1] + b1;
            out[(size_t)(r + 8) * En + cc]     = c[mf][nf][2] + b0;
            out[(size_t)(r + 8) * En + cc + 1] = c[mf][nf][3] + b1;
        }
    }
}

// ---------------- launch ----------------
extern "C" void kernel_launch(void* const* d_in, const int* in_sizes, int n_in,
                              void* d_out, int out_size)
{
    const float* query     = (const float*)d_in[0];
    const float* key       = (const float*)d_in[1];
    const float* value     = (const float*)d_in[2];
    const float* a_sum_mem = (const float*)d_in[3];
    const float* av_mem    = (const float*)d_in[4];
    const float* q_mem     = (const float*)d_in[5];
    const float* k_t_mem   = (const float*)d_in[6];
    const float* v_mem     = (const float*)d_in[7];
    const float* ipw       = (const float*)d_in[8];
    const float* ipb       = (const float*)d_in[9];
    const float* opw       = (const float*)d_in[10];
    const float* opb       = (const float*)d_in[11];

    float* out       = (float*)d_out;
    float* a_sum_out = out + (size_t)Nn * Bn * En;
    float* av_out    = a_sum_out + (size_t)BHn * NM1n;
    float* q_out     = av_out + (size_t)BHn * NM1n * EHn;
    float* kt_out    = q_out + (size_t)BHn * Nn * EHn;
    float* v_out     = kt_out + (size_t)BHn * Nn * EHn;

    wround_kernel<<<En * En / 1024, 256>>>(opw);
    proj_kernel<<<6144, 256>>>(query, key, value, ipw, ipb);
    atb_kernel<<<dim3(BHn, 4), 256>>>(k_t_mem, kt_out);
    alr_kernel<<<dim3(BHn, 4), 256>>>(q_mem, k_t_mem, q_out);
    avbot_kernel<<<dim3(BHn, 8), 256>>>(v_mem, v_out);
    ew_kernel<<<BHn * Nn / 4, 256>>>(a_sum_mem, av_mem, v_mem, a_sum_out, av_out);
    dim3 g(En / 128, (Nn * Bn) / 128);
    gemm_kernel<<<g, 256>>>(opb, out);
}